// round 7
// baseline (speedup 1.0000x reference)
#include <cuda_runtime.h>
#include <cuda_fp16.h>
#include <math.h>
#include <stdint.h>

#define BB 16
#define C1 128
#define C2 128
#define HH 64
#define WW 64
#define K2 9

// scratch
__device__ float  g_offmask[BB * 27 * HH * WW];                    // [b][ch][h][w]
__device__ __align__(16) __half g_x16[(size_t)BB * HH * WW * C1];  // [b][h][w][c] fp16
__device__ __align__(16) __half g_wk16[K2 * C2 * C1];              // [n][oc][c]
__device__ __align__(16) __half g_wom16[K2 * 32 * C1];             // [n][oc(27+pad)][c]

// ---------------------------------------------------------------------------
__device__ __forceinline__ uint32_t smem_u32(const void* p) {
    uint32_t a;
    asm("{ .reg .u64 t; cvta.to.shared.u64 t, %1; cvt.u32.u64 %0, t; }" : "=r"(a) : "l"(p));
    return a;
}
__device__ __forceinline__ void ldsm4(uint32_t addr, uint32_t* r) {
    asm volatile("ldmatrix.sync.aligned.m8n8.x4.shared.b16 {%0,%1,%2,%3}, [%4];"
                 : "=r"(r[0]), "=r"(r[1]), "=r"(r[2]), "=r"(r[3]) : "r"(addr));
}
__device__ __forceinline__ void mma16816(float* c, const uint32_t* a, uint32_t b0, uint32_t b1) {
    asm volatile("mma.sync.aligned.m16n8k16.row.col.f32.f16.f16.f32 "
                 "{%0,%1,%2,%3}, {%4,%5,%6,%7}, {%8,%9}, {%0,%1,%2,%3};"
                 : "+f"(c[0]), "+f"(c[1]), "+f"(c[2]), "+f"(c[3])
                 : "r"(a[0]), "r"(a[1]), "r"(a[2]), "r"(a[3]), "r"(b0), "r"(b1));
}
__device__ __forceinline__ void sts16(uint32_t addr, uint32_t a, uint32_t b, uint32_t c, uint32_t d) {
    asm volatile("st.shared.v4.b32 [%0], {%1,%2,%3,%4};" :: "r"(addr), "r"(a), "r"(b), "r"(c), "r"(d) : "memory");
}

// ---------------------------------------------------------------------------
// prep 1: x[b][c][hw] -> g_x16[b][hw][c] (fp16 channels-last)
// ---------------------------------------------------------------------------
__global__ void __launch_bounds__(256) x16_kernel(const float* __restrict__ x) {
    __shared__ float t[128][33];
    const int b = blockIdx.y;
    const int pix0 = blockIdx.x * 32;
    const int px = threadIdx.x & 31, c0 = threadIdx.x >> 5;
#pragma unroll
    for (int k = 0; k < 16; k++) {
        int c = c0 + k * 8;
        t[c][px] = x[((size_t)(b * C1 + c) << 12) + pix0 + px];
    }
    __syncthreads();
    const int pix = threadIdx.x >> 3, cq = threadIdx.x & 7;
    __half* dst = g_x16 + ((((size_t)b << 12) + pix0 + pix) << 7);
#pragma unroll
    for (int k = 0; k < 4; k++) {
        int ce = (cq + k * 8) * 4;
        __half2 h0 = __floats2half2_rn(t[ce][pix], t[ce + 1][pix]);
        __half2 h1 = __floats2half2_rn(t[ce + 2][pix], t[ce + 3][pix]);
        uint2 v;
        v.x = *(uint32_t*)&h0;
        v.y = *(uint32_t*)&h1;
        *(uint2*)(dst + ce) = v;
    }
}

// ---------------------------------------------------------------------------
// prep 2: w_conv[oc][c][n] -> g_wk16[n][oc][c]
// ---------------------------------------------------------------------------
__global__ void wk16_kernel(const float* __restrict__ w_conv) {
    int i = blockIdx.x * 256 + threadIdx.x;
    if (i < K2 * C2 * C1) {
        int n = i / (C2 * C1);
        int r = i % (C2 * C1);
        int oc = r / C1, c = r % C1;
        g_wk16[i] = __float2half(w_conv[(oc * C1 + c) * K2 + n]);
    }
}

// ---------------------------------------------------------------------------
// prep 3: w_off[18][c][n], w_mask[9][c][n] -> g_wom16[n][oc32][c]
// ---------------------------------------------------------------------------
__global__ void wom16_kernel(const float* __restrict__ w_off, const float* __restrict__ w_mask) {
    int i = blockIdx.x * 256 + threadIdx.x;
    if (i < K2 * 32 * C1) {
        int n = i / (32 * C1);
        int r = i % (32 * C1);
        int oc = r / C1, c = r % C1;
        float v = 0.f;
        if (oc < 18)      v = w_off[(oc * C1 + c) * K2 + n];
        else if (oc < 27) v = w_mask[((oc - 18) * C1 + c) * K2 + n];
        g_wom16[i] = __float2half(v);
    }
}

// ---------------------------------------------------------------------------
// offset/mask conv GEMM with resident halo A tile.
// CTA = 256 pixels (4 h-rows) x 32 outputs, 256 threads. Halo A tile built
// ONCE: 6 h-rows x 66 w (zero halo) x 128 c = 105 KB. Tap shift = row offset
// via per-lane ldmatrix addresses. B tiles double-buffered. ~125 KB smem.
// ---------------------------------------------------------------------------
#define QSA 136
#define Q_A   0
#define Q_B0  107712                      // 396 * 272
#define Q_B1  (Q_B0 + 8704)
#define Q_TOT (Q_B1 + 8704)               // 125120

__global__ void __launch_bounds__(256, 1) omg_kernel(
    const float* __restrict__ b_off, const float* __restrict__ b_mask)
{
    extern __shared__ char smem[];
    const uint32_t sb = smem_u32(smem);
    const int tid = threadIdx.x;
    const int lane = tid & 31;
    const int warp = tid >> 5;            // 8 warps = 8 m-groups of 32 pixels
    const int b = blockIdx.y;
    const int h0 = blockIdx.x * 4;

    // ---- fill halo A tile: 396 rows (6 h-rows x 66 w) ----
    for (int i = tid; i < 396 * 16; i += 256) {
        int r = i >> 4, s = i & 15;
        int hh = r / 66, ww = r - hh * 66;
        int h = h0 - 1 + hh, w = ww - 1;
        uint4 v = make_uint4(0, 0, 0, 0);
        if ((unsigned)h < HH && (unsigned)w < WW)
            v = *(const uint4*)(g_x16 + ((((size_t)(b << 12)) + (h << 6) + w) << 7) + s * 8);
        sts16(sb + Q_A + (uint32_t)(r * 272 + s * 16), v.x, v.y, v.z, v.w);
    }
    // ---- B tile for tap 0 (512 segs, 2 per thread) ----
#pragma unroll
    for (int k = 0; k < 2; k++) {
        int idx = tid + k * 256;
        uint4 v = ((const uint4*)g_wom16)[idx];
        sts16(sb + Q_B0 + (uint32_t)((idx >> 4) * 272 + (idx & 15) * 16), v.x, v.y, v.z, v.w);
    }
    __syncthreads();

    float acc[2][4][4];
#pragma unroll
    for (int i = 0; i < 2; i++)
#pragma unroll
        for (int j = 0; j < 4; j++)
#pragma unroll
            for (int k = 0; k < 4; k++) acc[i][j][k] = 0.f;

    const int pixA0 = warp * 32 + (lane & 15);
    const int pixA1 = pixA0 + 16;
    const int rA0 = ((pixA0 >> 6) + 1) * 66 + (pixA0 & 63) + 1;
    const int rA1 = ((pixA1 >> 6) + 1) * 66 + (pixA1 & 63) + 1;
    const uint32_t cbase = (uint32_t)((lane >> 4) << 3);
    const int rB = lane & 15;

    for (int n = 0; n < 9; n++) {
        uint4 bv0, bv1;
        if (n < 8) {
            bv0 = ((const uint4*)g_wom16)[(n + 1) * 512 + tid];
            bv1 = ((const uint4*)g_wom16)[(n + 1) * 512 + tid + 256];
        }
        const int shift = (n / 3 - 1) * 66 + (n % 3 - 1);
        const uint32_t aB = sb + Q_A;
        const uint32_t bB = sb + ((n & 1) ? Q_B1 : Q_B0);
#pragma unroll 2
        for (int kk = 0; kk < 8; kk++) {
            uint32_t col = kk * 16 + cbase;
            uint32_t a0[4], a1[4], bf0[4], bf1[4];
            ldsm4(aB + (uint32_t)(((rA0 + shift) * QSA + col) * 2), a0);
            ldsm4(aB + (uint32_t)(((rA1 + shift) * QSA + col) * 2), a1);
            ldsm4(bB + (uint32_t)((rB * QSA + col) * 2), bf0);
            ldsm4(bB + (uint32_t)(((rB + 16) * QSA + col) * 2), bf1);
            mma16816(acc[0][0], a0, bf0[0], bf0[2]);
            mma16816(acc[0][1], a0, bf0[1], bf0[3]);
            mma16816(acc[0][2], a0, bf1[0], bf1[2]);
            mma16816(acc[0][3], a0, bf1[1], bf1[3]);
            mma16816(acc[1][0], a1, bf0[0], bf0[2]);
            mma16816(acc[1][1], a1, bf0[1], bf0[3]);
            mma16816(acc[1][2], a1, bf1[0], bf1[2]);
            mma16816(acc[1][3], a1, bf1[1], bf1[3]);
        }
        if (n < 8) {
            uint32_t dstB = sb + (((n + 1) & 1) ? Q_B1 : Q_B0);
            sts16(dstB + (uint32_t)((tid >> 4) * 272 + (tid & 15) * 16),
                  bv0.x, bv0.y, bv0.z, bv0.w);
            int idx = tid + 256;
            sts16(dstB + (uint32_t)((idx >> 4) * 272 + (idx & 15) * 16),
                  bv1.x, bv1.y, bv1.z, bv1.w);
        }
        __syncthreads();
    }

    // epilogue: bias + sigmoid(mask) -> g_offmask[b][ch][h][w]
#pragma unroll
    for (int mt = 0; mt < 2; mt++) {
#pragma unroll
        for (int nt = 0; nt < 4; nt++) {
            const float* c = acc[mt][nt];
            int m0 = warp * 32 + mt * 16 + (lane >> 2);
            int n0 = nt * 8 + (lane & 3) * 2;
#pragma unroll
            for (int q = 0; q < 4; q++) {
                int pix = m0 + (q >> 1) * 8;
                int oc = n0 + (q & 1);
                if (oc >= 27) continue;
                float v = c[q];
                if (oc < 18) v += b_off[oc];
                else         v = 1.f / (1.f + __expf(-(v + b_mask[oc - 18])));
                int h = h0 + (pix >> 6), w = pix & 63;
                g_offmask[((b * 27 + oc) << 12) + (h << 6) + w] = v;
            }
        }
    }
}

// ---------------------------------------------------------------------------
// main DCN: 128 pixels x 128 oc, double-buffered A+B tiles AND per-tap
// metadata; offmask inputs prefetched one tap ahead into registers.
// ~144 KB smem, peak live set ~192 regs.
// ---------------------------------------------------------------------------
#define DSA 136
#define D_A0  0
#define D_A1  34816
#define D_B0  69632
#define D_B1  104448
#define D_M0  139264                     // int4[128] + float4[128] = 4096
#define D_M1  143360
#define D_TOT 147456

__device__ __forceinline__ void compute_meta(
    int n, int pix, int b, int h0, float offY, float offX, float m,
    int4* mI, float4* mW)
{
    const int h = h0 + (pix >> 6), w = pix & 63;
    float py = offY + (float)(h - 1 + n / 3);
    float px = offX + (float)(w - 1 + n % 3);
    float fy = floorf(py), fx = floorf(px);
    int y0 = (int)fy, x0 = (int)fx;
    float wy1 = py - fy, wx1 = px - fx;
    float wy0 = 1.f - wy1, wx0 = 1.f - wx1;
    int y1 = y0 + 1, x1 = x0 + 1;
    bool vy0 = (y0 >= 0) & (y0 < HH), vy1 = (y1 >= 0) & (y1 < HH);
    bool vx0 = (x0 >= 0) & (x0 < WW), vx1 = (x1 >= 0) & (x1 < WW);
    int y0c = min(max(y0, 0), HH - 1), y1c = min(max(y1, 0), HH - 1);
    int x0c = min(max(x0, 0), WW - 1), x1c = min(max(x1, 0), WW - 1);
    int base = (b << 12);
    mI[pix] = make_int4((base + (y0c << 6) + x0c) << 7,
                        (base + (y0c << 6) + x1c) << 7,
                        (base + (y1c << 6) + x0c) << 7,
                        (base + (y1c << 6) + x1c) << 7);
    mW[pix] = make_float4((vy0 && vx0) ? wy0 * wx0 * m : 0.f,
                          (vy0 && vx1) ? wy0 * wx1 * m : 0.f,
                          (vy1 && vx0) ? wy1 * wx0 * m : 0.f,
                          (vy1 && vx1) ? wy1 * wx1 * m : 0.f);
}

__global__ void __launch_bounds__(256, 1) dcn_kernel(float* __restrict__ out)
{
    extern __shared__ char smem[];
    const uint32_t sb = smem_u32(smem);

    const int tid = threadIdx.x;
    const int lane = tid & 31;
    const int warp = tid >> 5;
    const int warp_m = warp & 3;
    const int warp_n = warp >> 2;
    const int b = blockIdx.x >> 5;
    const int h0 = (blockIdx.x & 31) << 1;

    const float* omB = g_offmask + ((size_t)b * 27 << 12)
                     + ((h0 + (tid >> 6)) << 6) + (tid & 63);   // valid for tid<128

    float acc[2][8][4];
#pragma unroll
    for (int i = 0; i < 2; i++)
#pragma unroll
        for (int j = 0; j < 8; j++)
#pragma unroll
            for (int k = 0; k < 4; k++) acc[i][j][k] = 0.f;

    const int gpix_q = tid >> 3;
    const int chq = tid & 7;

    uint4 raw[4][4];
    uint4 bq[8];
    uint32_t stage[8][4];
    float pOffY = 0.f, pOffX = 0.f, pM = 0.f;   // prefetched offmask for next tap

#define GATHER_CHUNK(mIp, half)                                              \
    _Pragma("unroll")                                                        \
    for (int p = 0; p < 4; p++) {                                            \
        const int pp = p + (half) * 4;                                       \
        const int pix = (pp >> 1) * 32 + gpix_q;                             \
        const int seg = chq + (pp & 1) * 8;                                  \
        const int4 mi = (mIp)[pix];                                          \
        raw[p][0] = *(const uint4*)(g_x16 + mi.x + seg * 8);                 \
        raw[p][1] = *(const uint4*)(g_x16 + mi.y + seg * 8);                 \
        raw[p][2] = *(const uint4*)(g_x16 + mi.z + seg * 8);                 \
        raw[p][3] = *(const uint4*)(g_x16 + mi.w + seg * 8);                 \
    }

#define CONVERT_CHUNK(mWp, half)                                             \
    _Pragma("unroll")                                                        \
    for (int p = 0; p < 4; p++) {                                            \
        const int pp = p + (half) * 4;                                       \
        const int pix = (pp >> 1) * 32 + gpix_q;                             \
        const float4 mw = (mWp)[pix];                                        \
        _Pragma("unroll")                                                    \
        for (int q = 0; q < 4; q++) {                                        \
            float2 fa = __half22float2(((const __half2*)&raw[p][0])[q]);     \
            float2 fb = __half22float2(((const __half2*)&raw[p][1])[q]);     \
            float2 fc = __half22float2(((const __half2*)&raw[p][2])[q]);     \
            float2 fd = __half22float2(((const __half2*)&raw[p][3])[q]);     \
            float rx = mw.x * fa.x + mw.y * fb.x + mw.z * fc.x + mw.w * fd.x;\
            float ry = mw.x * fa.y + mw.y * fb.y + mw.z * fc.y + mw.w * fd.y;\
            __half2 hr = __floats2half2_rn(rx, ry);                          \
            stage[pp][q] = *(uint32_t*)&hr;                                  \
        }                                                                    \
    }

    // ---- prologue: meta(0), tap-0 gather+convert, B(0), prefetch om(1) ----
    if (tid < 128) {
        float oy = omB[(size_t)0];
        float ox = omB[(size_t)1 << 12];
        float mm = omB[(size_t)18 << 12];
        compute_meta(0, tid, b, h0, oy, ox, mm, (int4*)(smem + D_M0), (float4*)(smem + D_M0 + 2048));
    }
    __syncthreads();
    {
        int4*   mI = (int4*)(smem + D_M0);
        float4* mW = (float4*)(smem + D_M0 + 2048);
        GATHER_CHUNK(mI, 0);
        CONVERT_CHUNK(mW, 0);
        GATHER_CHUNK(mI, 1);
        CONVERT_CHUNK(mW, 1);
    }
#pragma unroll
    for (int k = 0; k < 8; k++)
        bq[k] = ((const uint4*)g_wk16)[tid + k * 256];
    if (tid < 128) {
        pOffY = omB[(size_t)2 << 12];
        pOffX = omB[(size_t)3 << 12];
        pM    = omB[(size_t)19 << 12];
    }

    const uint32_t rA = (uint32_t)(warp_m * 32 + (lane & 15));
    const uint32_t rB = (uint32_t)(warp_n * 64 + (lane & 15));
    const uint32_t cbase = (uint32_t)((lane >> 4) << 3);

    for (int n = 0; n < 9; n++) {
        const uint32_t aBuf = sb + ((n & 1) ? D_A1 : D_A0);
        const uint32_t bBuf = sb + ((n & 1) ? D_B1 : D_B0);
        char* mNext = smem + (((n + 1) & 1) ? D_M1 : D_M0);
        int4*   mI1 = (int4*)mNext;
        float4* mW1 = (float4*)(mNext + 2048);

        // ---- store staged tiles ----
#pragma unroll
        for (int pp = 0; pp < 8; pp++) {
            const int pix = (pp >> 1) * 32 + gpix_q;
            const int seg = chq + (pp & 1) * 8;
            sts16(aBuf + (uint32_t)((pix * DSA + seg * 8) * 2),
                  stage[pp][0], stage[pp][1], stage[pp][2], stage[pp][3]);
        }
#pragma unroll
        for (int k = 0; k < 8; k++) {
            const int idx = tid + k * 256;
            sts16(bBuf + (uint32_t)(((idx >> 4) * DSA + (idx & 15) * 8) * 2),
                  bq[k].x, bq[k].y, bq[k].z, bq[k].w);
        }
        // ---- meta for next tap from prefetched regs ----
        if (n < 8 && tid < 128)
            compute_meta(n + 1, tid, b, h0, pOffY, pOffX, pM, mI1, mW1);
        __syncthreads();

        // ---- gather chunk 0 (next tap), prefetch om(n+2) ----
        if (n < 8) { GATHER_CHUNK(mI1, 0); }
        if (n < 7 && tid < 128) {
            pOffY = omB[(size_t)(2 * (n + 2)) << 12];
            pOffX = omB[(size_t)(2 * (n + 2) + 1) << 12];
            pM    = omB[(size_t)(18 + n + 2) << 12];
        }

        // ---- MMA kk = 0..3 ----
#pragma unroll
        for (int kk = 0; kk < 4; kk++) {
            uint32_t col = kk * 16 + cbase;
            uint32_t a0[4], a1[4];
            ldsm4(aBuf + (rA * DSA + col) * 2, a0);
            ldsm4(aBuf + ((rA + 16) * DSA + col) * 2, a1);
            uint32_t bf[4][4];
#pragma unroll
            for (int t = 0; t < 4; t++)
                ldsm4(bBuf + ((rB + t * 16) * DSA + col) * 2, bf[t]);
#pragma unroll
            for (int t = 0; t < 4; t++) {
                mma16816(acc[0][2 * t],     a0, bf[t][0], bf[t][2]);
                mma16816(acc[0][2 * t + 1], a0, bf[t][1], bf[t][3]);
                mma16816(acc[1][2 * t],     a1, bf[t][0], bf[t][2]);
                mma16816(acc[1][2 * t + 1], a1, bf[t][1], bf[t][3]);
            }
        }

        // ---- convert chunk 0, gather chunk 1 ----
        if (n < 8) {
            CONVERT_CHUNK(mW1, 0);
            GATHER_CHUNK(mI1, 1);
        }

        // ---- MMA kk = 4..7 ----
#pragma unroll
        for (int kk = 4; kk < 8; kk++) {
            uint32_t col = kk * 16 + cbase;
            uint32_t a0[4], a1[4];
            ldsm4(aBuf + (rA * DSA + col) * 2, a0);
            ldsm4(aBuf + ((rA + 16) * DSA + col) * 2, a1);
            uint32_t bf[4][4];
#pragma unroll
            for (int t = 0; t < 4; t++)
                ldsm4(bBuf + ((rB + t * 16) * DSA + col) * 2, bf[t]);
#pragma unroll
            for (int t = 0; t < 4; t++) {
                mma16816(acc[0][2 * t],     a0, bf[t][0], bf[t][2]);
                mma16816(acc[0][2 * t + 1], a0, bf[t][1], bf[t][3]);
                mma16816(acc[1][2 * t],     a1, bf[t][0], bf[t][2]);
                mma16816(acc[1][2 * t + 1], a1, bf[t][1], bf[t][3]);
            }
        }

        // ---- convert chunk 1, prefetch next B ----
        if (n < 8) {
            CONVERT_CHUNK(mW1, 1);
#pragma unroll
            for (int k = 0; k < 8; k++)
                bq[k] = ((const uint4*)g_wk16)[(n + 1) * 2048 + tid + k * 256];
        }
    }

    // ---- epilogue ----
    const size_t obase = ((size_t)b * C2 << 12) + (size_t)h0 * 64;
#pragma unroll
    for (int mt = 0; mt < 2; mt++) {
#pragma unroll
        for (int nt = 0; nt < 8; nt++) {
            const float* c = acc[mt][nt];
            int m0 = warp_m * 32 + mt * 16 + (lane >> 2);
            int n0 = warp_n * 64 + nt * 8 + (lane & 3) * 2;
            float* o0 = out + obase + ((size_t)n0 << 12);
            float* o1 = o0 + 4096;
            o0[m0]     = c[0];
            o1[m0]     = c[1];
            o0[m0 + 8] = c[2];
            o1[m0 + 8] = c[3];
        }
    }
}

// ---------------------------------------------------------------------------
extern "C" void kernel_launch(void* const* d_in, const int* in_sizes, int n_in,
                              void* d_out, int out_size) {
    const float* x      = (const float*)d_in[0];
    const float* w_conv = (const float*)d_in[1];
    const float* w_off  = (const float*)d_in[2];
    const float* b_off  = (const float*)d_in[3];
    const float* w_mask = (const float*)d_in[4];
    const float* b_mask = (const float*)d_in[5];
    float* out = (float*)d_out;

    cudaFuncSetAttribute(dcn_kernel, cudaFuncAttributeMaxDynamicSharedMemorySize, D_TOT);
    cudaFuncSetAttribute(omg_kernel, cudaFuncAttributeMaxDynamicSharedMemorySize, Q_TOT);

    wk16_kernel<<<(K2 * C2 * C1 + 255) / 256, 256>>>(w_conv);
    wom16_kernel<<<(K2 * 32 * C1 + 255) / 256, 256>>>(w_off, w_mask);

    dim3 gT(HH * WW / 32, BB);
    x16_kernel<<<gT, 256>>>(x);

    dim3 gO(HH / 4, BB);
    omg_kernel<<<gO, 256, Q_TOT>>>(b_off, b_mask);

    dcn_kernel<<<BB * HH / 2, 256, D_TOT>>>(out);
}